// round 1
// baseline (speedup 1.0000x reference)
#include <cuda_runtime.h>
#include <math.h>

#define NN 100000
#define EE 1600000
#define KC 128      // IN_C and HID (both 128)
#define HIDC 128
#define OC 64

// ---- device scratch (no allocations allowed) ----
__device__ int   g_deg[NN];
__device__ float g_dinv[NN];
__device__ int   g_colptr[NN + 1];
__device__ int   g_fill[NN];
__device__ int   g_srcv[EE];
__device__ float g_wv[EE];
__device__ float g_h [(size_t)NN * HIDC];  // x @ W1
__device__ float g_a [(size_t)NN * HIDC];  // relu(agg1 + b1)
__device__ float g_h2[(size_t)NN * OC];    // g_a @ W2
__device__ int   g_is64;

// ---- dtype detection: int64 edge_index has zero high words (values < 2^31) ----
__global__ void k_detect(const int* __restrict__ ei32) {
    __shared__ int nz;
    if (threadIdx.x == 0) nz = 0;
    __syncthreads();
    for (int i = threadIdx.x; i < 4096; i += blockDim.x) {
        if (ei32[2 * i + 1] != 0) nz = 1;  // benign race
    }
    __syncthreads();
    if (threadIdx.x == 0) g_is64 = nz ? 0 : 1;
}

__device__ __forceinline__ int edge_at(const void* ei, size_t idx, int is64) {
    if (is64) return (int)((const long long*)ei)[idx];
    return ((const int*)ei)[idx];
}

__global__ void k_zero_deg() {
    int i = blockIdx.x * blockDim.x + threadIdx.x;
    if (i < NN) g_deg[i] = 0;
}

__global__ void k_count(const void* __restrict__ ei) {
    int e = blockIdx.x * blockDim.x + threadIdx.x;
    if (e >= EE) return;
    int is64 = g_is64;
    int c = edge_at(ei, (size_t)EE + e, is64);
    atomicAdd(&g_deg[c], 1);
}

__global__ void k_dinv() {
    int i = blockIdx.x * blockDim.x + threadIdx.x;
    if (i < NN) {
        int d = g_deg[i];
        g_dinv[i] = (d > 0) ? 1.0f / sqrtf((float)d) : 0.0f;
    }
}

// single-block exclusive scan of g_deg -> g_colptr / g_fill
__global__ void k_scan() {
    __shared__ int sh[1024];
    const int T = 1024;
    const int CH = (NN + T - 1) / T;  // 98
    int t = threadIdx.x;
    int lo = t * CH;
    int hi = min(lo + CH, NN);
    int s = 0;
    for (int i = lo; i < hi; i++) s += g_deg[i];
    sh[t] = s;
    __syncthreads();
    for (int off = 1; off < T; off <<= 1) {
        int v = 0;
        if (t >= off) v = sh[t - off];
        __syncthreads();
        if (t >= off) sh[t] += v;
        __syncthreads();
    }
    int run = sh[t] - s;  // exclusive prefix
    for (int i = lo; i < hi; i++) {
        g_colptr[i] = run;
        g_fill[i]   = run;
        run += g_deg[i];
    }
    if (t == T - 1) g_colptr[NN] = sh[T - 1];
}

__global__ void k_build(const void* __restrict__ ei) {
    int e = blockIdx.x * blockDim.x + threadIdx.x;
    if (e >= EE) return;
    int is64 = g_is64;
    int r = edge_at(ei, (size_t)e, is64);
    int c = edge_at(ei, (size_t)EE + e, is64);
    float w = g_dinv[r] * g_dinv[c];
    int pos = atomicAdd(&g_fill[c], 1);
    g_srcv[pos] = r;
    g_wv[pos]   = w;
}

// ---- SGEMM: Y[NN,OUTC] = X[NN,128] @ W[128,OUTC], 64x64 tile, 4x4/thread ----
template <int OUTC>
__global__ __launch_bounds__(256) void k_gemm(const float* __restrict__ X,
                                              const float* __restrict__ W,
                                              float* __restrict__ Y) {
    __shared__ float xs[64 * 64];  // xs[kk*64 + r]
    __shared__ float ws[64 * 64];  // ws[kk*64 + c]
    int row0 = blockIdx.x * 64;
    int col0 = blockIdx.y * 64;
    int tid  = threadIdx.x;
    int tr = (tid >> 4) << 2;   // 0..60
    int tc = (tid & 15) << 2;   // 0..60
    float acc[4][4] = {};

    for (int kb = 0; kb < KC; kb += 64) {
        // load W chunk: consecutive tid -> consecutive c (coalesced)
        for (int i = tid; i < 4096; i += 256) {
            int c = i & 63, kk = i >> 6;
            ws[kk * 64 + c] = W[(size_t)(kb + kk) * OUTC + col0 + c];
        }
        // load X chunk transposed: consecutive tid -> consecutive kk (coalesced)
        for (int i = tid; i < 4096; i += 256) {
            int kk = i & 63, r = i >> 6;
            int gr = row0 + r;
            xs[kk * 64 + r] = (gr < NN) ? X[(size_t)gr * KC + kb + kk] : 0.0f;
        }
        __syncthreads();
#pragma unroll 16
        for (int kk = 0; kk < 64; kk++) {
            float4 xv = *(const float4*)&xs[kk * 64 + tr];
            float4 wv = *(const float4*)&ws[kk * 64 + tc];
            acc[0][0] = fmaf(xv.x, wv.x, acc[0][0]);
            acc[0][1] = fmaf(xv.x, wv.y, acc[0][1]);
            acc[0][2] = fmaf(xv.x, wv.z, acc[0][2]);
            acc[0][3] = fmaf(xv.x, wv.w, acc[0][3]);
            acc[1][0] = fmaf(xv.y, wv.x, acc[1][0]);
            acc[1][1] = fmaf(xv.y, wv.y, acc[1][1]);
            acc[1][2] = fmaf(xv.y, wv.z, acc[1][2]);
            acc[1][3] = fmaf(xv.y, wv.w, acc[1][3]);
            acc[2][0] = fmaf(xv.z, wv.x, acc[2][0]);
            acc[2][1] = fmaf(xv.z, wv.y, acc[2][1]);
            acc[2][2] = fmaf(xv.z, wv.z, acc[2][2]);
            acc[2][3] = fmaf(xv.z, wv.w, acc[2][3]);
            acc[3][0] = fmaf(xv.w, wv.x, acc[3][0]);
            acc[3][1] = fmaf(xv.w, wv.y, acc[3][1]);
            acc[3][2] = fmaf(xv.w, wv.z, acc[3][2]);
            acc[3][3] = fmaf(xv.w, wv.w, acc[3][3]);
        }
        __syncthreads();
    }
    for (int i = 0; i < 4; i++) {
        int gr = row0 + tr + i;
        if (gr < NN) {
            float4 o = make_float4(acc[i][0], acc[i][1], acc[i][2], acc[i][3]);
            *(float4*)&Y[(size_t)gr * OUTC + col0 + tc] = o;
        }
    }
}

// ---- aggregation conv1: warp per node, 128 channels (float4/lane), +b1, relu ----
__global__ __launch_bounds__(256) void k_agg1(const float* __restrict__ b) {
    int gw   = (blockIdx.x * blockDim.x + threadIdx.x) >> 5;
    int lane = threadIdx.x & 31;
    if (gw >= NN) return;
    int s0 = g_colptr[gw], s1 = g_colptr[gw + 1];
    const float4* h4 = (const float4*)g_h;
    float4 acc = make_float4(0.f, 0.f, 0.f, 0.f);
    for (int e = s0; e < s1; e++) {
        int   s = g_srcv[e];   // uniform across warp (broadcast)
        float w = g_wv[e];
        float4 hv = h4[(size_t)s * 32 + lane];
        acc.x = fmaf(hv.x, w, acc.x);
        acc.y = fmaf(hv.y, w, acc.y);
        acc.z = fmaf(hv.z, w, acc.z);
        acc.w = fmaf(hv.w, w, acc.w);
    }
    float4 bv = ((const float4*)b)[lane];
    acc.x = fmaxf(acc.x + bv.x, 0.f);
    acc.y = fmaxf(acc.y + bv.y, 0.f);
    acc.z = fmaxf(acc.z + bv.z, 0.f);
    acc.w = fmaxf(acc.w + bv.w, 0.f);
    ((float4*)g_a)[(size_t)gw * 32 + lane] = acc;
}

// ---- aggregation conv2: warp per node, 64 channels (float2/lane), +b2 ----
__global__ __launch_bounds__(256) void k_agg2(const float* __restrict__ b,
                                              float* __restrict__ out) {
    int gw   = (blockIdx.x * blockDim.x + threadIdx.x) >> 5;
    int lane = threadIdx.x & 31;
    if (gw >= NN) return;
    int s0 = g_colptr[gw], s1 = g_colptr[gw + 1];
    const float2* h2 = (const float2*)g_h2;
    float2 acc = make_float2(0.f, 0.f);
    for (int e = s0; e < s1; e++) {
        int   s = g_srcv[e];
        float w = g_wv[e];
        float2 hv = h2[(size_t)s * 32 + lane];
        acc.x = fmaf(hv.x, w, acc.x);
        acc.y = fmaf(hv.y, w, acc.y);
    }
    float2 bv = ((const float2*)b)[lane];
    acc.x += bv.x;
    acc.y += bv.y;
    ((float2*)out)[(size_t)gw * 32 + lane] = acc;
}

extern "C" void kernel_launch(void* const* d_in, const int* in_sizes, int n_in,
                              void* d_out, int out_size) {
    const float* x  = (const float*)d_in[0];
    const void*  ei = d_in[1];
    const float* W1 = (const float*)d_in[2];
    const float* b1 = (const float*)d_in[3];
    const float* W2 = (const float*)d_in[4];
    const float* b2 = (const float*)d_in[5];
    float* out = (float*)d_out;

    float *ph, *pa, *ph2;
    cudaGetSymbolAddress((void**)&ph,  g_h);
    cudaGetSymbolAddress((void**)&pa,  g_a);
    cudaGetSymbolAddress((void**)&ph2, g_h2);

    const int TB = 256;
    k_detect<<<1, 256>>>((const int*)ei);
    k_zero_deg<<<(NN + TB - 1) / TB, TB>>>();
    k_count<<<(EE + TB - 1) / TB, TB>>>(ei);
    k_dinv<<<(NN + TB - 1) / TB, TB>>>();
    k_scan<<<1, 1024>>>();
    k_build<<<(EE + TB - 1) / TB, TB>>>(ei);

    // conv1: h = x @ W1 ; a = relu(agg(h) + b1)
    k_gemm<HIDC><<<dim3((NN + 63) / 64, HIDC / 64), 256>>>(x, W1, ph);
    k_agg1<<<((NN * 32) + TB - 1) / TB, TB>>>(b1);

    // conv2: h2 = a @ W2 ; out = agg(h2) + b2
    k_gemm<OC><<<dim3((NN + 63) / 64, OC / 64), 256>>>(pa, W2, ph2);
    k_agg2<<<((NN * 32) + TB - 1) / TB, TB>>>(b2, out);
}